// round 14
// baseline (speedup 1.0000x reference)
#include <cuda_runtime.h>

// Problem constants
#define BB   32
#define NN   2048
#define DD   65
#define HH   64
#define DSQ  (DD*DD)        // 4225
#define GCH  64             // gram chunk rows per block
#define NGC  (NN/GCH)       // 32 partials per batch
#define OCH  128            // out chunk rows
#define NOC  (NN/OCH)       // 16
#define OP   72             // padded dim for tensor k_out (9 tiles of 8)

typedef unsigned long long ull;

// Scratch (no allocations allowed)
__device__ float g_Gpart[BB * NGC * DSQ];   // partial Gram matrices (~17.3 MB)
__device__ float g_G[BB * DSQ];             // reduced Gram
__device__ float g_M[BB * DSQ];             // M = A * G * Wv^T per batch

// ---- packed fp32x2 helpers ----
__device__ __forceinline__ ull pack2(float x) {
    ull d; unsigned u = __float_as_uint(x);
    asm("mov.b64 %0, {%1, %1};" : "=l"(d) : "r"(u));
    return d;
}
__device__ __forceinline__ ull fma2(ull a, ull b, ull c) {
    ull d;
    asm("fma.rn.f32x2 %0, %1, %2, %3;" : "=l"(d) : "l"(a), "l"(b), "l"(c));
    return d;
}
__device__ __forceinline__ void unpack2(ull d, float& lo, float& hi) {
    unsigned a, b;
    asm("mov.b64 {%0, %1}, %2;" : "=r"(a), "=r"(b) : "l"(d));
    lo = __uint_as_float(a); hi = __uint_as_float(b);
}

// ---- tf32 helpers ----
__device__ __forceinline__ unsigned f2tf32(float v) {
    unsigned r; asm("cvt.rna.tf32.f32 %0, %1;" : "=r"(r) : "f"(v)); return r;
}
__device__ __forceinline__ void mma_tf32(float* d, const unsigned* a,
                                         unsigned b0, unsigned b1) {
    asm volatile(
        "mma.sync.aligned.m16n8k8.row.col.f32.tf32.tf32.f32 "
        "{%0,%1,%2,%3}, {%4,%5,%6,%7}, {%8,%9}, {%0,%1,%2,%3};"
        : "+f"(d[0]), "+f"(d[1]), "+f"(d[2]), "+f"(d[3])
        : "r"(a[0]), "r"(a[1]), "r"(a[2]), "r"(a[3]), "r"(b0), "r"(b1));
}

// ---------------------------------------------------------------------------
// Kernel 1 (proven): partial Gram, 64-row chunk, FFMA2 dup-buffer.
// grid (32, 32), block 256, dynamic smem 58368 B.
// ---------------------------------------------------------------------------
__global__ void __launch_bounds__(256) k_gram(const float* __restrict__ x) {
    extern __shared__ __align__(16) float smg[];
    float* xs   = smg;               // 64*68
    float* xdup = smg + GCH * 68;    // 64*160

    const int b = blockIdx.y, c = blockIdx.x;
    const int tid = threadIdx.x;
    const float* xp = x + ((size_t)b * NN + (size_t)c * GCH) * DD;

    for (int idx = tid; idx < GCH * DD; idx += 256) {
        int r = idx / DD, col = idx - r * DD;
        float v = xp[idx];
        xs[r * 68 + col] = v;
        xdup[r * 160 + 2 * col]     = v;
        xdup[r * 160 + 2 * col + 1] = v;
    }
    __syncthreads();

    const int ty = tid >> 4, tx = tid & 15;
    const int p0 = tx, p1 = 16 + tx, p2 = (tx == 0) ? 32 : 33;

    ull acc[5][3];
#pragma unroll
    for (int u = 0; u < 5; ++u)
#pragma unroll
        for (int v = 0; v < 3; ++v) acc[u][v] = 0ull;

#pragma unroll 4
    for (int k = 0; k < GCH; ++k) {
        const ull* xd = (const ull*)(xs + k * 68);
        const ull* ar = (const ull*)(xdup + k * 160);
        ull b0 = xd[p0], b1 = xd[p1], b2 = xd[p2];
#pragma unroll
        for (int u = 0; u < 5; ++u) {
            ull ad = ar[ty + 16 * u];
            acc[u][0] = fma2(ad, b0, acc[u][0]);
            acc[u][1] = fma2(ad, b1, acc[u][1]);
            acc[u][2] = fma2(ad, b2, acc[u][2]);
        }
    }

    float* gp = g_Gpart + (size_t)(b * NGC + c) * DSQ;
    const int pv[3] = {p0, p1, p2};
#pragma unroll
    for (int u = 0; u < 5; ++u) {
        int i = ty + 16 * u;
        if (i >= DD) continue;
#pragma unroll
        for (int v = 0; v < 3; ++v) {
            int j0 = 2 * pv[v];
            float lo, hi;
            unpack2(acc[u][v], lo, hi);
            if (j0     < DD) gp[i * DD + j0]     = lo;
            if (j0 + 1 < DD) gp[i * DD + j0 + 1] = hi;
        }
    }
}

// ---------------------------------------------------------------------------
// Kernel 2: reduce 32 partial Grams -> g_G.  grid (17, 32). (proven)
// ---------------------------------------------------------------------------
__global__ void k_reduce() {
    const int b = blockIdx.y;
    int idx = blockIdx.x * 256 + threadIdx.x;
    if (idx >= DSQ) return;
    const float* gp = g_Gpart + (size_t)b * NGC * DSQ + idx;
    float s0 = 0.f, s1 = 0.f, s2 = 0.f, s3 = 0.f;
#pragma unroll
    for (int c = 0; c < NGC; c += 4) {
        s0 += gp[(c + 0) * DSQ];
        s1 += gp[(c + 1) * DSQ];
        s2 += gp[(c + 2) * DSQ];
        s3 += gp[(c + 3) * DSQ];
    }
    g_G[b * DSQ + idx] = (s0 + s1) + (s2 + s3);
}

// ---------------------------------------------------------------------------
// Kernel 3 (proven): mid chain, tiled 3 ways per batch. grid (3, 32).
// ---------------------------------------------------------------------------
__global__ void __launch_bounds__(256) k_mid3(const float* __restrict__ Wq,
                                              const float* __restrict__ Wk,
                                              const float* __restrict__ Wv) {
    __shared__ __align__(16) float B1[DD * 68];
    __shared__ __align__(16) float B2[DD * 68];
    __shared__ __align__(16) float B3[32 * 68];

    const int b = blockIdx.y, t = blockIdx.x;
    const int tid = threadIdx.x;
    const int ty = tid >> 4, tx = tid & 15;
    const int p0 = tx, p1 = 16 + tx, p2 = (tx == 0) ? 32 : 33;
    const int pv[3] = {p0, p1, p2};
    const int i0 = t * 32;

    int iv[2];
#pragma unroll
    for (int u = 0; u < 2; ++u) {
        int i = i0 + ty + 16 * u;
        iv[u] = (i < DD) ? i : (DD - 1);
    }

    for (int idx = tid; idx < HH * DD; idx += 256) {
        int h = idx / DD, i = idx - h * DD;
        B1[h * 68 + i] = Wq[idx];
        B2[h * 68 + i] = Wk[idx];
    }
    __syncthreads();

    // phase 0: A-tile
    {
        ull acc[2][3];
#pragma unroll
        for (int u = 0; u < 2; ++u)
#pragma unroll
            for (int v = 0; v < 3; ++v) acc[u][v] = 0ull;
#pragma unroll 8
        for (int h = 0; h < HH; ++h) {
            const ull* kr = (const ull*)(B2 + h * 68);
            ull b0 = kr[p0], b1 = kr[p1], b2 = kr[p2];
            const float* qr = B1 + h * 68;
#pragma unroll
            for (int u = 0; u < 2; ++u) {
                ull ad = pack2(qr[iv[u]]);
                acc[u][0] = fma2(ad, b0, acc[u][0]);
                acc[u][1] = fma2(ad, b1, acc[u][1]);
                acc[u][2] = fma2(ad, b2, acc[u][2]);
            }
        }
        __syncthreads();
#pragma unroll
        for (int u = 0; u < 2; ++u) {
            ull* ap = (ull*)(B3 + (ty + 16 * u) * 68);
#pragma unroll
            for (int v = 0; v < 3; ++v) ap[pv[v]] = acc[u][v];
        }
    }
    for (int idx = tid; idx < DSQ; idx += 256) {
        int k = idx / DD, j = idx - k * DD;
        B2[k * 68 + j] = g_G[(size_t)b * DSQ + idx];
    }
    __syncthreads();

    // phase 1: T-tile = A-tile * G
    ull accT[2][3];
#pragma unroll
    for (int u = 0; u < 2; ++u)
#pragma unroll
        for (int v = 0; v < 3; ++v) accT[u][v] = 0ull;
#pragma unroll 5
    for (int k = 0; k < DD; ++k) {
        const ull* gr = (const ull*)(B2 + k * 68);
        ull b0 = gr[p0], b1 = gr[p1], b2 = gr[p2];
#pragma unroll
        for (int u = 0; u < 2; ++u) {
            ull ad = pack2(B3[(ty + 16 * u) * 68 + k]);
            accT[u][0] = fma2(ad, b0, accT[u][0]);
            accT[u][1] = fma2(ad, b1, accT[u][1]);
            accT[u][2] = fma2(ad, b2, accT[u][2]);
        }
    }
    __syncthreads();

#pragma unroll
    for (int u = 0; u < 2; ++u) {
        ull* tp = (ull*)(B3 + (ty + 16 * u) * 68);
#pragma unroll
        for (int v = 0; v < 3; ++v) tp[pv[v]] = accT[u][v];
    }
    for (int idx = tid; idx < DSQ; idx += 256) {
        int j = idx / DD, k = idx - j * DD;
        B1[k * 68 + j] = Wv[idx];
    }
    __syncthreads();

    // phase 2: M-tile = T-tile * Wv^T
    {
        ull acc[2][3];
#pragma unroll
        for (int u = 0; u < 2; ++u)
#pragma unroll
            for (int v = 0; v < 3; ++v) acc[u][v] = 0ull;
#pragma unroll 5
        for (int k = 0; k < DD; ++k) {
            const ull* wr = (const ull*)(B1 + k * 68);
            ull b0 = wr[p0], b1 = wr[p1], b2 = wr[p2];
#pragma unroll
            for (int u = 0; u < 2; ++u) {
                ull ad = pack2(B3[(ty + 16 * u) * 68 + k]);
                acc[u][0] = fma2(ad, b0, acc[u][0]);
                acc[u][1] = fma2(ad, b1, acc[u][1]);
                acc[u][2] = fma2(ad, b2, acc[u][2]);
            }
        }
        float* Mb = g_M + (size_t)b * DSQ;
#pragma unroll
        for (int u = 0; u < 2; ++u) {
            int i = i0 + ty + 16 * u;
            if (i >= DD) continue;
#pragma unroll
            for (int v = 0; v < 3; ++v) {
                int j0 = 2 * pv[v];
                float lo, hi;
                unpack2(acc[u][v], lo, hi);
                if (j0     < DD) Mb[i * DD + j0]     = lo;
                if (j0 + 1 < DD) Mb[i * DD + j0 + 1] = hi;
            }
        }
    }
}

// ---------------------------------------------------------------------------
// Kernel 4 (NEW, tensor core): out_chunk = x_chunk * M_b via tf32 mma.sync
// with 3-term split (hi+lo). grid (16, 32), block 256 (8 warps).
// Warp w owns rows [16w, 16w+16); 9 n-tiles x 9 k-tiles x 3 mmas.
// smem: xs[128][72] fp32 | Mhi[72][72] tf32 | Mlo[72][72] tf32 (78336 B).
// All pads zeroed (no NaN leakage). Epilogue staged via xs, coalesced STG.
// ---------------------------------------------------------------------------
__global__ void __launch_bounds__(256) k_out(const float* __restrict__ x,
                                             float* __restrict__ out) {
    extern __shared__ __align__(16) float smo[];
    float* xs  = smo;                      // 128*72
    float* Mhi = smo + OCH * OP;           // 72*72
    float* Mlo = Mhi + OP * OP;            // 72*72

    const int b = blockIdx.y, c = blockIdx.x;
    const float* xp = x + ((size_t)b * NN + (size_t)c * OCH) * DD;
    float* op = out + ((size_t)b * NN + (size_t)c * OCH) * DD;
    const int tid = threadIdx.x;

    // zero pads: whole M buffers + xs pad columns
    for (int idx = tid; idx < OP * OP; idx += 256) {
        Mhi[idx] = 0.f;
        Mlo[idx] = 0.f;
    }
    for (int idx = tid; idx < OCH * (OP - DD); idx += 256) {
        int r = idx / (OP - DD), t = idx % (OP - DD);
        xs[r * OP + DD + t] = 0.f;
    }
    __syncthreads();

    // stage x (fp32) and M (pre-split tf32 hi/lo)
    for (int idx = tid; idx < OCH * DD; idx += 256) {
        int r = idx / DD, k = idx - r * DD;
        xs[r * OP + k] = xp[idx];
    }
    const float* Mg = g_M + (size_t)b * DSQ;
    for (int idx = tid; idx < DSQ; idx += 256) {
        int k = idx / DD, j = idx - k * DD;
        float v = Mg[idx];
        unsigned hi = f2tf32(v);
        float lof = v - __uint_as_float(hi);
        unsigned lo = f2tf32(lof);
        Mhi[k * OP + j] = __uint_as_float(hi);
        Mlo[k * OP + j] = __uint_as_float(lo);
    }
    __syncthreads();

    const int warp = tid >> 5, lane = tid & 31;
    const int grp = lane >> 2, tig = lane & 3;
    const int m0 = warp * 16;

    float acc[9][4];
#pragma unroll
    for (int nt = 0; nt < 9; ++nt)
#pragma unroll
        for (int q = 0; q < 4; ++q) acc[nt][q] = 0.f;

#pragma unroll
    for (int kt = 0; kt < 9; ++kt) {
        const int k0 = kt * 8;
        // A fragment (m16 x k8, row-major) + hi/lo split
        float av[4];
        av[0] = xs[(m0 + grp)     * OP + k0 + tig];
        av[1] = xs[(m0 + grp + 8) * OP + k0 + tig];
        av[2] = xs[(m0 + grp)     * OP + k0 + tig + 4];
        av[3] = xs[(m0 + grp + 8) * OP + k0 + tig + 4];
        unsigned ahi[4], alo[4];
#pragma unroll
        for (int q = 0; q < 4; ++q) {
            ahi[q] = f2tf32(av[q]);
            alo[q] = f2tf32(av[q] - __uint_as_float(ahi[q]));
        }
#pragma unroll
        for (int nt = 0; nt < 9; ++nt) {
            const int n0 = nt * 8;
            // B fragment (k8 x n8): b0 at (k0+tig, n0+grp), b1 at (k0+tig+4, n0+grp)
            unsigned bh0 = __float_as_uint(Mhi[(k0 + tig)     * OP + n0 + grp]);
            unsigned bh1 = __float_as_uint(Mhi[(k0 + tig + 4) * OP + n0 + grp]);
            unsigned bl0 = __float_as_uint(Mlo[(k0 + tig)     * OP + n0 + grp]);
            unsigned bl1 = __float_as_uint(Mlo[(k0 + tig + 4) * OP + n0 + grp]);
            mma_tf32(acc[nt], ahi, bh0, bh1);
            mma_tf32(acc[nt], ahi, bl0, bl1);
            mma_tf32(acc[nt], alo, bh0, bh1);
        }
    }

    __syncthreads();   // all xs reads done; reuse as output staging
    float* osm = xs;   // 128*65 fits in 128*72

#pragma unroll
    for (int nt = 0; nt < 9; ++nt) {
        const int n0 = nt * 8;
        int col0 = n0 + 2 * tig;
        int r0 = m0 + grp;
        if (col0 < DD) {
            osm[r0 * DD + col0]       = acc[nt][0];
            osm[(r0 + 8) * DD + col0] = acc[nt][2];
        }
        if (col0 + 1 < DD) {
            osm[r0 * DD + col0 + 1]       = acc[nt][1];
            osm[(r0 + 8) * DD + col0 + 1] = acc[nt][3];
        }
    }
    __syncthreads();

    for (int idx = tid; idx < OCH * DD; idx += 256)
        op[idx] = osm[idx];
}

// ---------------------------------------------------------------------------
extern "C" void kernel_launch(void* const* d_in, const int* in_sizes, int n_in,
                              void* d_out, int out_size) {
    const float* x  = (const float*)d_in[0];   // [32, 2048, 65]
    const float* Wq = (const float*)d_in[1];   // [64, 65]
    const float* Wk = (const float*)d_in[2];   // [64, 65]
    const float* Wv = (const float*)d_in[3];   // [65, 65]
    float* out = (float*)d_out;                // [32, 2048, 65]

    const int smem_gram = (GCH * 68 + GCH * 160) * 4;        // 58368 B
    const int smem_out  = (OCH * OP + 2 * OP * OP) * 4;      // 78336 B
    cudaFuncSetAttribute(k_gram, cudaFuncAttributeMaxDynamicSharedMemorySize, smem_gram);
    cudaFuncSetAttribute(k_out,  cudaFuncAttributeMaxDynamicSharedMemorySize, smem_out);

    k_gram<<<dim3(NGC, BB), 256, smem_gram>>>(x);
    k_reduce<<<dim3(17, BB), 256>>>();
    k_mid3<<<dim3(3, BB), 256>>>(Wq, Wk, Wv);
    k_out<<<dim3(NOC, BB), 256, smem_out>>>(x, out);
}

// round 15
// speedup vs baseline: 1.0324x; 1.0324x over previous
#include <cuda_runtime.h>

// Problem constants
#define BB   32
#define NN   2048
#define DD   65
#define HH   64
#define DSQ  (DD*DD)        // 4225
#define GCH  64             // gram chunk rows per block
#define NGC  (NN/GCH)       // 32 partials per batch
#define OCH  128            // out chunk rows
#define NOC  (NN/OCH)       // 16
#define OP   72             // padded dim for tensor k_out (9 tiles of 8)

typedef unsigned long long ull;

// Scratch (no allocations allowed)
__device__ float g_Gpart[BB * NGC * DSQ];   // partial Gram matrices (~17.3 MB)
__device__ float g_G[BB * DSQ];             // reduced Gram
__device__ float g_M[BB * DSQ];             // M = A * G * Wv^T per batch

// ---- packed fp32x2 helpers ----
__device__ __forceinline__ ull pack2(float x) {
    ull d; unsigned u = __float_as_uint(x);
    asm("mov.b64 %0, {%1, %1};" : "=l"(d) : "r"(u));
    return d;
}
__device__ __forceinline__ ull fma2(ull a, ull b, ull c) {
    ull d;
    asm("fma.rn.f32x2 %0, %1, %2, %3;" : "=l"(d) : "l"(a), "l"(b), "l"(c));
    return d;
}
__device__ __forceinline__ void unpack2(ull d, float& lo, float& hi) {
    unsigned a, b;
    asm("mov.b64 {%0, %1}, %2;" : "=r"(a), "=r"(b) : "l"(d));
    lo = __uint_as_float(a); hi = __uint_as_float(b);
}

// ---- tf32 helpers ----
__device__ __forceinline__ unsigned f2tf32(float v) {
    unsigned r; asm("cvt.rna.tf32.f32 %0, %1;" : "=r"(r) : "f"(v)); return r;
}
__device__ __forceinline__ void mma_tf32(float* d, const unsigned* a,
                                         unsigned b0, unsigned b1) {
    asm volatile(
        "mma.sync.aligned.m16n8k8.row.col.f32.tf32.tf32.f32 "
        "{%0,%1,%2,%3}, {%4,%5,%6,%7}, {%8,%9}, {%0,%1,%2,%3};"
        : "+f"(d[0]), "+f"(d[1]), "+f"(d[2]), "+f"(d[3])
        : "r"(a[0]), "r"(a[1]), "r"(a[2]), "r"(a[3]), "r"(b0), "r"(b1));
}

// ---------------------------------------------------------------------------
// Kernel 1 (proven): partial Gram, 64-row chunk, FFMA2 dup-buffer.
// grid (32, 32), block 256, dynamic smem 58368 B.
// ---------------------------------------------------------------------------
__global__ void __launch_bounds__(256) k_gram(const float* __restrict__ x) {
    extern __shared__ __align__(16) float smg[];
    float* xs   = smg;               // 64*68
    float* xdup = smg + GCH * 68;    // 64*160

    const int b = blockIdx.y, c = blockIdx.x;
    const int tid = threadIdx.x;
    const float* xp = x + ((size_t)b * NN + (size_t)c * GCH) * DD;

    for (int idx = tid; idx < GCH * DD; idx += 256) {
        int r = idx / DD, col = idx - r * DD;
        float v = xp[idx];
        xs[r * 68 + col] = v;
        xdup[r * 160 + 2 * col]     = v;
        xdup[r * 160 + 2 * col + 1] = v;
    }
    __syncthreads();

    const int ty = tid >> 4, tx = tid & 15;
    const int p0 = tx, p1 = 16 + tx, p2 = (tx == 0) ? 32 : 33;

    ull acc[5][3];
#pragma unroll
    for (int u = 0; u < 5; ++u)
#pragma unroll
        for (int v = 0; v < 3; ++v) acc[u][v] = 0ull;

#pragma unroll 4
    for (int k = 0; k < GCH; ++k) {
        const ull* xd = (const ull*)(xs + k * 68);
        const ull* ar = (const ull*)(xdup + k * 160);
        ull b0 = xd[p0], b1 = xd[p1], b2 = xd[p2];
#pragma unroll
        for (int u = 0; u < 5; ++u) {
            ull ad = ar[ty + 16 * u];
            acc[u][0] = fma2(ad, b0, acc[u][0]);
            acc[u][1] = fma2(ad, b1, acc[u][1]);
            acc[u][2] = fma2(ad, b2, acc[u][2]);
        }
    }

    float* gp = g_Gpart + (size_t)(b * NGC + c) * DSQ;
    const int pv[3] = {p0, p1, p2};
#pragma unroll
    for (int u = 0; u < 5; ++u) {
        int i = ty + 16 * u;
        if (i >= DD) continue;
#pragma unroll
        for (int v = 0; v < 3; ++v) {
            int j0 = 2 * pv[v];
            float lo, hi;
            unpack2(acc[u][v], lo, hi);
            if (j0     < DD) gp[i * DD + j0]     = lo;
            if (j0 + 1 < DD) gp[i * DD + j0 + 1] = hi;
        }
    }
}

// ---------------------------------------------------------------------------
// Kernel 2: reduce 32 partial Grams -> g_G.  grid (17, 32). (proven)
// ---------------------------------------------------------------------------
__global__ void k_reduce() {
    const int b = blockIdx.y;
    int idx = blockIdx.x * 256 + threadIdx.x;
    if (idx >= DSQ) return;
    const float* gp = g_Gpart + (size_t)b * NGC * DSQ + idx;
    float s0 = 0.f, s1 = 0.f, s2 = 0.f, s3 = 0.f;
#pragma unroll
    for (int c = 0; c < NGC; c += 4) {
        s0 += gp[(c + 0) * DSQ];
        s1 += gp[(c + 1) * DSQ];
        s2 += gp[(c + 2) * DSQ];
        s3 += gp[(c + 3) * DSQ];
    }
    g_G[b * DSQ + idx] = (s0 + s1) + (s2 + s3);
}

// ---------------------------------------------------------------------------
// Kernel 3 (proven): mid chain, tiled 3 ways per batch. grid (3, 32).
// ---------------------------------------------------------------------------
__global__ void __launch_bounds__(256) k_mid3(const float* __restrict__ Wq,
                                              const float* __restrict__ Wk,
                                              const float* __restrict__ Wv) {
    __shared__ __align__(16) float B1[DD * 68];
    __shared__ __align__(16) float B2[DD * 68];
    __shared__ __align__(16) float B3[32 * 68];

    const int b = blockIdx.y, t = blockIdx.x;
    const int tid = threadIdx.x;
    const int ty = tid >> 4, tx = tid & 15;
    const int p0 = tx, p1 = 16 + tx, p2 = (tx == 0) ? 32 : 33;
    const int pv[3] = {p0, p1, p2};
    const int i0 = t * 32;

    int iv[2];
#pragma unroll
    for (int u = 0; u < 2; ++u) {
        int i = i0 + ty + 16 * u;
        iv[u] = (i < DD) ? i : (DD - 1);
    }

    for (int idx = tid; idx < HH * DD; idx += 256) {
        int h = idx / DD, i = idx - h * DD;
        B1[h * 68 + i] = Wq[idx];
        B2[h * 68 + i] = Wk[idx];
    }
    __syncthreads();

    // phase 0: A-tile
    {
        ull acc[2][3];
#pragma unroll
        for (int u = 0; u < 2; ++u)
#pragma unroll
            for (int v = 0; v < 3; ++v) acc[u][v] = 0ull;
#pragma unroll 8
        for (int h = 0; h < HH; ++h) {
            const ull* kr = (const ull*)(B2 + h * 68);
            ull b0 = kr[p0], b1 = kr[p1], b2 = kr[p2];
            const float* qr = B1 + h * 68;
#pragma unroll
            for (int u = 0; u < 2; ++u) {
                ull ad = pack2(qr[iv[u]]);
                acc[u][0] = fma2(ad, b0, acc[u][0]);
                acc[u][1] = fma2(ad, b1, acc[u][1]);
                acc[u][2] = fma2(ad, b2, acc[u][2]);
            }
        }
        __syncthreads();
#pragma unroll
        for (int u = 0; u < 2; ++u) {
            ull* ap = (ull*)(B3 + (ty + 16 * u) * 68);
#pragma unroll
            for (int v = 0; v < 3; ++v) ap[pv[v]] = acc[u][v];
        }
    }
    for (int idx = tid; idx < DSQ; idx += 256) {
        int k = idx / DD, j = idx - k * DD;
        B2[k * 68 + j] = g_G[(size_t)b * DSQ + idx];
    }
    __syncthreads();

    // phase 1: T-tile = A-tile * G
    ull accT[2][3];
#pragma unroll
    for (int u = 0; u < 2; ++u)
#pragma unroll
        for (int v = 0; v < 3; ++v) accT[u][v] = 0ull;
#pragma unroll 5
    for (int k = 0; k < DD; ++k) {
        const ull* gr = (const ull*)(B2 + k * 68);
        ull b0 = gr[p0], b1 = gr[p1], b2 = gr[p2];
#pragma unroll
        for (int u = 0; u < 2; ++u) {
            ull ad = pack2(B3[(ty + 16 * u) * 68 + k]);
            accT[u][0] = fma2(ad, b0, accT[u][0]);
            accT[u][1] = fma2(ad, b1, accT[u][1]);
            accT[u][2] = fma2(ad, b2, accT[u][2]);
        }
    }
    __syncthreads();

#pragma unroll
    for (int u = 0; u < 2; ++u) {
        ull* tp = (ull*)(B3 + (ty + 16 * u) * 68);
#pragma unroll
        for (int v = 0; v < 3; ++v) tp[pv[v]] = accT[u][v];
    }
    for (int idx = tid; idx < DSQ; idx += 256) {
        int j = idx / DD, k = idx - j * DD;
        B1[k * 68 + j] = Wv[idx];
    }
    __syncthreads();

    // phase 2: M-tile = T-tile * Wv^T
    {
        ull acc[2][3];
#pragma unroll
        for (int u = 0; u < 2; ++u)
#pragma unroll
            for (int v = 0; v < 3; ++v) acc[u][v] = 0ull;
#pragma unroll 5
        for (int k = 0; k < DD; ++k) {
            const ull* wr = (const ull*)(B1 + k * 68);
            ull b0 = wr[p0], b1 = wr[p1], b2 = wr[p2];
#pragma unroll
            for (int u = 0; u < 2; ++u) {
                ull ad = pack2(B3[(ty + 16 * u) * 68 + k]);
                acc[u][0] = fma2(ad, b0, acc[u][0]);
                acc[u][1] = fma2(ad, b1, acc[u][1]);
                acc[u][2] = fma2(ad, b2, acc[u][2]);
            }
        }
        float* Mb = g_M + (size_t)b * DSQ;
#pragma unroll
        for (int u = 0; u < 2; ++u) {
            int i = i0 + ty + 16 * u;
            if (i >= DD) continue;
#pragma unroll
            for (int v = 0; v < 3; ++v) {
                int j0 = 2 * pv[v];
                float lo, hi;
                unpack2(acc[u][v], lo, hi);
                if (j0     < DD) Mb[i * DD + j0]     = lo;
                if (j0 + 1 < DD) Mb[i * DD + j0 + 1] = hi;
            }
        }
    }
}

// ---------------------------------------------------------------------------
// Kernel 4 (tensor core v2): out = x * M via tf32 mma.sync, 3-term split.
// grid (16, 32), block 256 (8 warps), OCH=128.
// CHANGES vs v1: no xs smem (A-fragments loaded straight from global with
// k<65 predicate — each x element is consumed exactly once, smem bought no
// reuse); smem = Mhi|Mlo only (41.5 KB), epilogue osm aliases Mhi;
// __launch_bounds__(256,3) -> 24 warps/SM (was 16).
// ---------------------------------------------------------------------------
__global__ void __launch_bounds__(256, 3) k_out(const float* __restrict__ x,
                                                float* __restrict__ out) {
    extern __shared__ __align__(16) float smo[];
    float* Mhi = smo;                 // 72*72
    float* Mlo = smo + OP * OP;       // 72*72
    float* osm = smo;                 // alias: reused after mainloop (128*65 <= 2*72*72)

    const int b = blockIdx.y, c = blockIdx.x;
    const float* xp = x + ((size_t)b * NN + (size_t)c * OCH) * DD;
    float* op = out + ((size_t)b * NN + (size_t)c * OCH) * DD;
    const int tid = threadIdx.x;

    // zero pads (whole M buffers), then stage pre-split M
    for (int idx = tid; idx < OP * OP; idx += 256) {
        Mhi[idx] = 0.f;
        Mlo[idx] = 0.f;
    }
    __syncthreads();
    const float* Mg = g_M + (size_t)b * DSQ;
    for (int idx = tid; idx < DSQ; idx += 256) {
        int k = idx / DD, j = idx - k * DD;
        float v = Mg[idx];
        unsigned hi = f2tf32(v);
        float lof = v - __uint_as_float(hi);
        Mhi[k * OP + j] = __uint_as_float(hi);
        Mlo[k * OP + j] = __uint_as_float(f2tf32(lof));
    }
    __syncthreads();

    const int warp = tid >> 5, lane = tid & 31;
    const int grp = lane >> 2, tig = lane & 3;
    const int m0 = warp * 16;
    const float* xr0 = xp + (m0 + grp) * DD;       // row m0+grp
    const float* xr8 = xp + (m0 + grp + 8) * DD;   // row m0+grp+8

    float acc[9][4];
#pragma unroll
    for (int nt = 0; nt < 9; ++nt)
#pragma unroll
        for (int q = 0; q < 4; ++q) acc[nt][q] = 0.f;

#pragma unroll
    for (int kt = 0; kt < 9; ++kt) {
        const int ka = kt * 8 + tig;       // <= 67
        const int kb = ka + 4;             // <= 71
        // A fragment from GLOBAL, predicated (pads = 0)
        float av[4];
        av[0] = (ka < DD) ? __ldg(xr0 + ka) : 0.f;
        av[1] = (ka < DD) ? __ldg(xr8 + ka) : 0.f;
        av[2] = (kb < DD) ? __ldg(xr0 + kb) : 0.f;
        av[3] = (kb < DD) ? __ldg(xr8 + kb) : 0.f;
        unsigned ahi[4], alo[4];
#pragma unroll
        for (int q = 0; q < 4; ++q) {
            ahi[q] = f2tf32(av[q]);
            alo[q] = f2tf32(av[q] - __uint_as_float(ahi[q]));
        }
        const int k0 = kt * 8;
#pragma unroll
        for (int nt = 0; nt < 9; ++nt) {
            const int n0 = nt * 8;
            unsigned bh0 = __float_as_uint(Mhi[(k0 + tig)     * OP + n0 + grp]);
            unsigned bh1 = __float_as_uint(Mhi[(k0 + tig + 4) * OP + n0 + grp]);
            unsigned bl0 = __float_as_uint(Mlo[(k0 + tig)     * OP + n0 + grp]);
            unsigned bl1 = __float_as_uint(Mlo[(k0 + tig + 4) * OP + n0 + grp]);
            mma_tf32(acc[nt], ahi, bh0, bh1);
            mma_tf32(acc[nt], ahi, bl0, bl1);
            mma_tf32(acc[nt], alo, bh0, bh1);
        }
    }

    __syncthreads();   // all Mhi/Mlo reads done; reuse as output staging

#pragma unroll
    for (int nt = 0; nt < 9; ++nt) {
        const int n0 = nt * 8;
        int col0 = n0 + 2 * tig;
        int r0 = m0 + grp;
        if (col0 < DD) {
            osm[r0 * DD + col0]       = acc[nt][0];
            osm[(r0 + 8) * DD + col0] = acc[nt][2];
        }
        if (col0 + 1 < DD) {
            osm[r0 * DD + col0 + 1]       = acc[nt][1];
            osm[(r0 + 8) * DD + col0 + 1] = acc[nt][3];
        }
    }
    __syncthreads();

    for (int idx = tid; idx < OCH * DD; idx += 256)
        op[idx] = osm[idx];
}

// ---------------------------------------------------------------------------
extern "C" void kernel_launch(void* const* d_in, const int* in_sizes, int n_in,
                              void* d_out, int out_size) {
    const float* x  = (const float*)d_in[0];   // [32, 2048, 65]
    const float* Wq = (const float*)d_in[1];   // [64, 65]
    const float* Wk = (const float*)d_in[2];   // [64, 65]
    const float* Wv = (const float*)d_in[3];   // [65, 65]
    float* out = (float*)d_out;                // [32, 2048, 65]

    const int smem_gram = (GCH * 68 + GCH * 160) * 4;   // 58368 B
    const int smem_out  = (2 * OP * OP) * 4;            // 41472 B
    cudaFuncSetAttribute(k_gram, cudaFuncAttributeMaxDynamicSharedMemorySize, smem_gram);
    cudaFuncSetAttribute(k_out,  cudaFuncAttributeMaxDynamicSharedMemorySize, smem_out);

    k_gram<<<dim3(NGC, BB), 256, smem_gram>>>(x);
    k_reduce<<<dim3(17, BB), 256>>>();
    k_mid3<<<dim3(3, BB), 256>>>(Wq, Wk, Wv);
    k_out<<<dim3(NOC, BB), 256, smem_out>>>(x, out);
}